// round 4
// baseline (speedup 1.0000x reference)
#include <cuda_runtime.h>
#include <math.h>

#define B 8
#define D 512
#define T 4096
#define CD 64
#define CS 1024
#define NSCALES 4
#define NROWS (B*D)
#define BT (B*T)
#define ZQ_ELEMS (B*D*T)                  // 16777216
#define CODES_ELEMS (B*NSCALES*T)         // 131072
#define LOSS_OFF (ZQ_ELEMS + CODES_ELEMS)
#define LOSS_MEAN_DENOM 2097152.0f        // B*CD*T

// ------------------------ scratch ------------------------
__device__ float g_residual[ZQ_ELEMS];        // 64MB
__device__ float g_zf[ZQ_ELEMS];              // 64MB
__device__ float g_ze[B*CD*T];                // 8MB
__device__ float g_WiT[NSCALES*D*CD];         // weight-normed in-proj, [d][c]
__device__ float g_WoT[NSCALES*CD*D];         // weight-normed out-proj, [c][d]
__device__ float g_cnp[NSCALES*CS*CD];        // normalized codebook, tile/pair-packed
__device__ float g_cnn[NSCALES*CS];           // ||cn_j||^2
__device__ int   g_idx[BT];                   // final codes for current scale
__device__ float g_partials[NSCALES*256];

// ------------------------ f32x2 helpers ------------------------
__device__ __forceinline__ void fma2(unsigned long long& acc,
                                     unsigned long long a, unsigned long long b) {
    asm("fma.rn.f32x2 %0, %1, %2, %0;" : "+l"(acc) : "l"(a), "l"(b));
}
__device__ __forceinline__ unsigned long long packf2(float lo, float hi) {
    unsigned long long r;
    asm("mov.b64 %0, {%1, %2};" : "=l"(r) : "f"(lo), "f"(hi));
    return r;
}
__device__ __forceinline__ float2 unpackf2(unsigned long long v) {
    float lo, hi;
    asm("mov.b64 {%0, %1}, %2;" : "=f"(lo), "=f"(hi) : "l"(v));
    return make_float2(lo, hi);
}

// ------------------------ complex helpers ------------------------
__device__ __forceinline__ float2 cadd(float2 a, float2 b){return make_float2(a.x+b.x, a.y+b.y);}
__device__ __forceinline__ float2 csub(float2 a, float2 b){return make_float2(a.x-b.x, a.y-b.y);}
__device__ __forceinline__ float2 cmul(float2 a, float2 b){
    return make_float2(a.x*b.x - a.y*b.y, a.x*b.y + a.y*b.x);}
__device__ __forceinline__ float2 cmulc(float2 a, float2 b){
    return make_float2(a.x*b.x + a.y*b.y, a.y*b.x - a.x*b.y);}
__device__ __forceinline__ float2 mulnegi(float2 a){return make_float2(a.y, -a.x);}
__device__ __forceinline__ float2 mulposi(float2 a){return make_float2(-a.y, a.x);}

// ------------------------ weight prep ------------------------
__global__ void prep_weights_kernel(const float* __restrict__ v_in,
                                    const float* __restrict__ g_in,
                                    const float* __restrict__ v_out,
                                    const float* __restrict__ g_out,
                                    const float* __restrict__ codebook)
{
    int blk = blockIdx.x;
    int sc = blk / 1600;
    int r  = blk % 1600;
    int tid = threadIdx.x;
    __shared__ float red[4];

    const float* src; int n; float g; int kind;
    if (r < 64) { src = v_in + (size_t)(sc*64 + r)*512; n = 512; g = g_in[sc*64 + r]; kind = 0; }
    else if (r < 576) { int d = r-64; src = v_out + (size_t)(sc*512 + d)*64; n = 64; g = g_out[sc*512 + d]; kind = 1; }
    else { src = codebook + (size_t)(sc*1024 + (r-576))*64; n = 64; g = 1.0f; kind = 2; }

    float ss = 0.f;
    for (int i = tid; i < n; i += 128) { float v = src[i]; ss = fmaf(v, v, ss); }
    #pragma unroll
    for (int o = 16; o; o >>= 1) ss += __shfl_xor_sync(~0u, ss, o);
    if ((tid & 31) == 0) red[tid >> 5] = ss;
    __syncthreads();
    float tot = red[0] + red[1] + red[2] + red[3];
    float inv = g / fmaxf(sqrtf(tot), 1e-12f);

    if (kind == 0) {
        int c = r;
        for (int i = tid; i < n; i += 128)
            g_WiT[((size_t)sc*512 + i)*64 + c] = src[i] * inv;
    } else if (kind == 1) {
        int d = r - 64;
        for (int i = tid; i < n; i += 128)
            g_WoT[((size_t)sc*64 + i)*512 + d] = src[i] * inv;
    } else {
        int j = r - 576;
        float ss2 = 0.f;
        for (int i = tid; i < n; i += 128) {
            float v = src[i] * inv;
            size_t fidx = ((((size_t)(sc*32 + (j>>5))*64 + i)*8 + ((j&31)>>2))*4) + (j&3);
            g_cnp[fidx] = v;
            ss2 = fmaf(v, v, ss2);
        }
        #pragma unroll
        for (int o = 16; o; o >>= 1) ss2 += __shfl_xor_sync(~0u, ss2, o);
        __syncthreads();
        if ((tid & 31) == 0) red[tid >> 5] = ss2;
        __syncthreads();
        if (tid == 0) g_cnn[sc*1024 + j] = red[0] + red[1] + red[2] + red[3];
    }
}

// ------------------------ FFT band filter (radix-4, 2 packed real rows) ------------------------
__global__ __launch_bounds__(512) void fft_filter_kernel(const float* __restrict__ zsrc, int use_z, int fl)
{
    __shared__ float2 s[4096];
    __shared__ float2 tw[2048];
    const float* src = use_z ? zsrc : g_residual;
    size_t roff = (size_t)blockIdx.x * 2 * T;
    const float* x0 = src + roff;
    const float* x1 = x0 + T;
    int tid = threadIdx.x;

    for (int i = tid; i < 4096; i += 512) s[i] = make_float2(x0[i], x1[i]);
    for (int k = tid; k < 2048; k += 512) {
        float sv, cv;
        sincospif((float)k * (-1.0f/2048.0f), &sv, &cv);
        tw[k] = make_float2(cv, sv);
    }
    __syncthreads();

    for (int logq = 10; logq >= 0; logq -= 2) {
        int q = 1 << logq;
        int tsh = 10 - logq;
        #pragma unroll
        for (int pp = 0; pp < 2; pp++) {
            int p = tid + pp*512;
            int j = p & (q - 1);
            int base = ((p >> logq) << (logq + 2)) | j;
            float2 a = s[base], b = s[base+q], c = s[base+2*q], d = s[base+3*q];
            float2 t0 = cadd(a, c), t1 = csub(a, c);
            float2 t2 = cadd(b, d), t3 = mulnegi(csub(b, d));
            int jt = j << tsh;
            float2 w1 = tw[jt], w2 = tw[2*jt], w3 = cmul(w1, w2);
            s[base]     = cadd(t0, t2);
            s[base+q]   = cmul(cadd(t1, t3), w1);
            s[base+2*q] = cmul(csub(t0, t2), w2);
            s[base+3*q] = cmul(csub(t1, t3), w3);
        }
        __syncthreads();
    }

    for (int p = tid; p < 4096; p += 512) {
        unsigned rb = __brev((unsigned)p) >> 20;
        int k = (int)(((rb & 0x555u) << 1) | ((rb >> 1) & 0x555u));
        if (!(k <= fl || k >= 4096 - fl)) s[p] = make_float2(0.f, 0.f);
    }
    __syncthreads();

    for (int logq = 0; logq <= 10; logq += 2) {
        int q = 1 << logq;
        int tsh = 10 - logq;
        #pragma unroll
        for (int pp = 0; pp < 2; pp++) {
            int p = tid + pp*512;
            int j = p & (q - 1);
            int base = ((p >> logq) << (logq + 2)) | j;
            int jt = j << tsh;
            float2 w1 = tw[jt], w2 = tw[2*jt], w3 = cmul(w1, w2);
            float2 a = s[base];
            float2 b = cmulc(s[base+q],   w1);
            float2 c = cmulc(s[base+2*q], w2);
            float2 d = cmulc(s[base+3*q], w3);
            float2 t0 = cadd(a, c), t1 = csub(a, c);
            float2 t2 = cadd(b, d), t3 = mulposi(csub(b, d));
            s[base]     = cadd(t0, t2);
            s[base+q]   = cadd(t1, t3);
            s[base+2*q] = csub(t0, t2);
            s[base+3*q] = csub(t1, t3);
        }
        __syncthreads();
    }

    float* y0 = g_zf + roff;
    float* y1 = y0 + T;
    const float scl = 1.0f / 4096.0f;
    for (int i = tid; i < 4096; i += 512) {
        float2 v = s[i];
        y0[i] = v.x * scl;
        y1[i] = v.y * scl;
    }
}

// ------------------------ FUSED in_proj + argmax ------------------------
// Block = 128 t-columns, 256 threads. Phase 1: in_proj GEMM (64c x 128t tile),
// z_e kept in smem + written to g_ze; inv2 reduced in smem. Phase 2: full
// 1024-code argmax over 16 j-tiles (64 codes each); final codes to g_idx.
// Dynamic smem: zs 8192f | pool 8192f | inv2s 128f = 66048 bytes.
__global__ __launch_bounds__(256) void proj_argmax_kernel(int sc, int use_zf,
    const float* __restrict__ b_in, float* __restrict__ codes_out)
{
    extern __shared__ float smem[];
    float* zs    = smem;              // [64][128]
    float* pool  = smem + 8192;       // phase1: zsm[32][128] | wsm[32][64] | red[128][8]
    float* inv2s = smem + 16384;      // [128]

    const float* src = use_zf ? g_zf : g_residual;
    int b = blockIdx.y, t0 = blockIdx.x * 128;
    int tid = threadIdx.x;
    int tx = tid & 31, ty = tid >> 5;     // phase-1 roles

    float* zsm = pool;                // 4096 floats
    float* wsm = pool + 4096;         // 2048 floats
    float* red = pool + 6144;         // 1024 floats [128][8]

    // ---------------- phase 1: in_proj ----------------
    unsigned long long acc[8][2];
    #pragma unroll
    for (int i = 0; i < 8; i++) { acc[i][0] = 0ull; acc[i][1] = 0ull; }

    for (int d0 = 0; d0 < D; d0 += 32) {
        for (int i = tid; i < 32*128; i += 256) {
            int dd = i >> 7, tt = i & 127;
            zsm[dd*128 + tt] = src[((size_t)(b*D + d0 + dd))*T + t0 + tt];
        }
        for (int i = tid; i < 32*64; i += 256) {
            int dd = i >> 6, c = i & 63;
            wsm[dd*64 + c] = g_WiT[((size_t)sc*512 + d0 + dd)*64 + c];
        }
        __syncthreads();
        #pragma unroll 8
        for (int dd = 0; dd < 32; dd++) {
            ulonglong2 z2 = *(const ulonglong2*)&zsm[dd*128 + 4*tx];
            float4 wa = *(const float4*)&wsm[dd*64 + 8*ty];
            float4 wb = *(const float4*)&wsm[dd*64 + 8*ty + 4];
            unsigned long long w0 = packf2(wa.x, wa.x), w1 = packf2(wa.y, wa.y);
            unsigned long long w2 = packf2(wa.z, wa.z), w3 = packf2(wa.w, wa.w);
            unsigned long long w4 = packf2(wb.x, wb.x), w5 = packf2(wb.y, wb.y);
            unsigned long long w6 = packf2(wb.z, wb.z), w7 = packf2(wb.w, wb.w);
            fma2(acc[0][0], w0, z2.x); fma2(acc[0][1], w0, z2.y);
            fma2(acc[1][0], w1, z2.x); fma2(acc[1][1], w1, z2.y);
            fma2(acc[2][0], w2, z2.x); fma2(acc[2][1], w2, z2.y);
            fma2(acc[3][0], w3, z2.x); fma2(acc[3][1], w3, z2.y);
            fma2(acc[4][0], w4, z2.x); fma2(acc[4][1], w4, z2.y);
            fma2(acc[5][0], w5, z2.x); fma2(acc[5][1], w5, z2.y);
            fma2(acc[6][0], w6, z2.x); fma2(acc[6][1], w6, z2.y);
            fma2(acc[7][0], w7, z2.x); fma2(acc[7][1], w7, z2.y);
        }
        __syncthreads();
    }

    float ss0 = 0.f, ss1 = 0.f, ss2 = 0.f, ss3 = 0.f;
    #pragma unroll
    for (int cc = 0; cc < 8; cc++) {
        int c = 8*ty + cc;
        float bb = b_in[sc*CD + c];
        float2 v0 = unpackf2(acc[cc][0]);
        float2 v1 = unpackf2(acc[cc][1]);
        float4 st = make_float4(v0.x + bb, v0.y + bb, v1.x + bb, v1.y + bb);
        *(float4*)&g_ze[((size_t)(b*CD + c))*T + t0 + 4*tx] = st;
        *(float4*)&zs[c*128 + 4*tx] = st;
        ss0 = fmaf(st.x, st.x, ss0);
        ss1 = fmaf(st.y, st.y, ss1);
        ss2 = fmaf(st.z, st.z, ss2);
        ss3 = fmaf(st.w, st.w, ss3);
    }
    red[(4*tx + 0)*8 + ty] = ss0;
    red[(4*tx + 1)*8 + ty] = ss1;
    red[(4*tx + 2)*8 + ty] = ss2;
    red[(4*tx + 3)*8 + ty] = ss3;
    __syncthreads();
    if (tid < 128) {
        float s = 0.f;
        #pragma unroll
        for (int w = 0; w < 8; w++) s += red[tid*8 + w];
        inv2s[tid] = 2.0f / fmaxf(sqrtf(s), 1e-12f);
    }
    // NOTE: no sync needed here; the tile-0 staging sync below publishes inv2s,
    // and staging writes pool[0..4095] which is disjoint from red/inv2s.

    // ---------------- phase 2: argmax over 1024 codes ----------------
    int tp = tid & 63, jg = tid >> 6;      // 2 t-cols per thread, 4 j-groups
    int tilesel = jg >> 1;                 // which 32-code subtile of the 64-tile
    int qh = (jg & 1) * 4;                 // quad offset within subtile
    const float* cnn = g_cnn + sc*CS;

    float best0 = -INFINITY, best1 = -INFINITY;
    int bi0 = 0, bi1 = 0;

    for (int jt = 0; jt < 16; jt++) {
        __syncthreads();   // previous pool readers done (and publishes inv2s at jt=0)
        {
            const float4* p = (const float4*)(g_cnp + (size_t)(sc*32 + jt*2)*2048);
            for (int l = tid; l < 1024; l += 256) ((float4*)pool)[l] = p[l];
        }
        __syncthreads();
        const ulonglong2* ws = (const ulonglong2*)pool;   // [2][64][8]

        unsigned long long a2[2][8];
        #pragma unroll
        for (int i = 0; i < 2; i++)
            #pragma unroll
            for (int m = 0; m < 8; m++) a2[i][m] = 0ull;

        #pragma unroll 4
        for (int c = 0; c < 64; c++) {
            float2 zf = *(const float2*)&zs[c*128 + 2*tp];
            unsigned long long zz0 = packf2(zf.x, zf.x);
            unsigned long long zz1 = packf2(zf.y, zf.y);
            int wb = (tilesel*64 + c)*8 + qh;
            #pragma unroll
            for (int q = 0; q < 4; q++) {
                ulonglong2 w = ws[wb + q];
                fma2(a2[0][2*q], w.x, zz0); fma2(a2[0][2*q+1], w.y, zz0);
                fma2(a2[1][2*q], w.x, zz1); fma2(a2[1][2*q+1], w.y, zz1);
            }
        }

        float iv0 = inv2s[2*tp], iv1 = inv2s[2*tp + 1];
        int jbase = jt*64 + tilesel*32 + qh*4;
        #pragma unroll
        for (int q = 0; q < 4; q++) {
            float n0 = cnn[jbase + 4*q + 0];
            float n1 = cnn[jbase + 4*q + 1];
            float n2 = cnn[jbase + 4*q + 2];
            float n3 = cnn[jbase + 4*q + 3];
            float2 d0 = unpackf2(a2[0][2*q]);
            float2 d1 = unpackf2(a2[0][2*q+1]);
            float s0 = fmaf(d0.x, iv0, -n0);
            float s1 = fmaf(d0.y, iv0, -n1);
            float s2 = fmaf(d1.x, iv0, -n2);
            float s3 = fmaf(d1.y, iv0, -n3);
            int j0 = jbase + 4*q;
            if (s0 > best0) { best0 = s0; bi0 = j0; }
            if (s1 > best0) { best0 = s1; bi0 = j0 + 1; }
            if (s2 > best0) { best0 = s2; bi0 = j0 + 2; }
            if (s3 > best0) { best0 = s3; bi0 = j0 + 3; }
            float2 e0 = unpackf2(a2[1][2*q]);
            float2 e1 = unpackf2(a2[1][2*q+1]);
            float u0 = fmaf(e0.x, iv1, -n0);
            float u1 = fmaf(e0.y, iv1, -n1);
            float u2 = fmaf(e1.x, iv1, -n2);
            float u3 = fmaf(e1.y, iv1, -n3);
            if (u0 > best1) { best1 = u0; bi1 = j0; }
            if (u1 > best1) { best1 = u1; bi1 = j0 + 1; }
            if (u2 > best1) { best1 = u2; bi1 = j0 + 2; }
            if (u3 > best1) { best1 = u3; bi1 = j0 + 3; }
        }
    }

    // cross-thread reduce over the 4 j-groups (min-index tie-break = first index)
    __syncthreads();
    float* rb = pool;                   // [128][4]
    int*   ri = (int*)(pool + 512);     // [128][4]
    rb[(2*tp + 0)*4 + jg] = best0;  ri[(2*tp + 0)*4 + jg] = bi0;
    rb[(2*tp + 1)*4 + jg] = best1;  ri[(2*tp + 1)*4 + jg] = bi1;
    __syncthreads();
    if (tid < 128) {
        float bv = -INFINITY; int bj = 0x7fffffff;
        #pragma unroll
        for (int k = 0; k < 4; k++) {
            float v = rb[tid*4 + k];
            int ix = ri[tid*4 + k];
            if (v > bv || (v == bv && ix < bj)) { bv = v; bj = ix; }
        }
        g_idx[b*T + t0 + tid] = bj;
        if (codes_out) codes_out[((size_t)(b*NSCALES + sc))*T + t0 + tid] = (float)bj;
    }
}

// ------------------------ loss + out_proj + residual ------------------------
__global__ __launch_bounds__(256) void loss_outproj_kernel(int sc, int mode,
    const float* __restrict__ cb_s, const float* __restrict__ b_out_s,
    const float* __restrict__ z, float* __restrict__ zq_out)
{
    __shared__ float cbs[64][128];     // 32KB, XOR-swizzled columns
    __shared__ float wpool[64*64];     // 16KB; start aliased by scodes + red
    int* scodes = (int*)wpool;         // [128]
    float* redp = wpool + 128;         // [8]
    int b = blockIdx.y, t0 = blockIdx.x * 128;
    int tid = threadIdx.x;
    int tx = tid & 31, ty = tid >> 5;

    if (tid < 128) scodes[tid] = g_idx[b*T + t0 + tid];
    __syncthreads();

    for (int i = tid; i < 64*128; i += 256) {
        int tt = i >> 6, c = i & 63;
        cbs[c][tt ^ ((c & 31) << 2)] = cb_s[scodes[tt]*64 + c];
    }
    __syncthreads();

    float ls = 0.f;
    for (int i = tid; i < 64*128; i += 256) {
        int c = i >> 7, tt = i & 127;
        float d = g_ze[((size_t)(b*CD + c))*T + t0 + tt] - cbs[c][tt ^ ((c & 31) << 2)];
        ls = fmaf(d, d, ls);
    }
    #pragma unroll
    for (int o = 16; o; o >>= 1) ls += __shfl_xor_sync(~0u, ls, o);
    if ((tid & 31) == 0) redp[tid >> 5] = ls;
    __syncthreads();
    if (tid == 0) {
        float tot = 0.f;
        #pragma unroll
        for (int w = 0; w < 8; w++) tot += redp[w];
        g_partials[sc*256 + b*32 + blockIdx.x] = tot;
    }

    for (int d0 = 0; d0 < D; d0 += 64) {
        __syncthreads();
        for (int i = tid; i < 64*64; i += 256) {
            int c = i >> 6, dd = i & 63;
            wpool[c*64 + dd] = g_WoT[((size_t)sc*64 + c)*512 + d0 + dd];
        }
        __syncthreads();

        unsigned long long acc[8][2];
        #pragma unroll
        for (int i = 0; i < 8; i++) { acc[i][0] = 0ull; acc[i][1] = 0ull; }
        #pragma unroll 8
        for (int c = 0; c < 64; c++) {
            ulonglong2 cb2 = *(const ulonglong2*)&cbs[c][(4*tx) ^ ((c & 31) << 2)];
            float4 wa = *(const float4*)&wpool[c*64 + 8*ty];
            float4 wb = *(const float4*)&wpool[c*64 + 8*ty + 4];
            unsigned long long w0 = packf2(wa.x, wa.x), w1 = packf2(wa.y, wa.y);
            unsigned long long w2 = packf2(wa.z, wa.z), w3 = packf2(wa.w, wa.w);
            unsigned long long w4 = packf2(wb.x, wb.x), w5 = packf2(wb.y, wb.y);
            unsigned long long w6 = packf2(wb.z, wb.z), w7 = packf2(wb.w, wb.w);
            fma2(acc[0][0], w0, cb2.x); fma2(acc[0][1], w0, cb2.y);
            fma2(acc[1][0], w1, cb2.x); fma2(acc[1][1], w1, cb2.y);
            fma2(acc[2][0], w2, cb2.x); fma2(acc[2][1], w2, cb2.y);
            fma2(acc[3][0], w3, cb2.x); fma2(acc[3][1], w3, cb2.y);
            fma2(acc[4][0], w4, cb2.x); fma2(acc[4][1], w4, cb2.y);
            fma2(acc[5][0], w5, cb2.x); fma2(acc[5][1], w5, cb2.y);
            fma2(acc[6][0], w6, cb2.x); fma2(acc[6][1], w6, cb2.y);
            fma2(acc[7][0], w7, cb2.x); fma2(acc[7][1], w7, cb2.y);
        }

        #pragma unroll
        for (int k = 0; k < 8; k++) {
            int d = d0 + 8*ty + k;
            float bb = b_out_s[d];
            float2 u0 = unpackf2(acc[k][0]);
            float2 u1 = unpackf2(acc[k][1]);
            float4 v = make_float4(u0.x + bb, u0.y + bb, u1.x + bb, u1.y + bb);
            size_t base = ((size_t)(b*D + d))*T + t0 + 4*tx;
            if (mode == 0) {
                float4 zv = *(const float4*)&z[base];
                float4 r = make_float4(zv.x - v.x, zv.y - v.y, zv.z - v.z, zv.w - v.w);
                *(float4*)&g_residual[base] = r;
            } else if (mode == 1) {
                float4 r = *(const float4*)&g_residual[base];
                r.x -= v.x; r.y -= v.y; r.z -= v.z; r.w -= v.w;
                *(float4*)&g_residual[base] = r;
            } else {
                float4 zv = *(const float4*)&z[base];
                float4 r = *(const float4*)&g_residual[base];
                float4 o = make_float4(zv.x - r.x + v.x, zv.y - r.y + v.y,
                                       zv.z - r.z + v.z, zv.w - r.w + v.w);
                *(float4*)&zq_out[base] = o;
            }
        }
    }
}

// ------------------------ final loss reduce ------------------------
__global__ void reduce_loss_kernel(float* __restrict__ out_loss)
{
    __shared__ float s[1024];
    int tid = threadIdx.x;
    float v = 0.f;
    for (int i = tid; i < NSCALES*256; i += 1024) v += g_partials[i];
    s[tid] = v;
    __syncthreads();
    for (int h = 512; h; h >>= 1) {
        if (tid < h) s[tid] += s[tid + h];
        __syncthreads();
    }
    if (tid == 0) {
        float m = s[0] / LOSS_MEAN_DENOM;
        out_loss[0] = m;
        out_loss[1] = m;
    }
}

// ------------------------ launch ------------------------
extern "C" void kernel_launch(void* const* d_in, const int* in_sizes, int n_in,
                              void* d_out, int out_size)
{
    const float* z     = (const float*)d_in[0];
    const float* v_in  = (const float*)d_in[1];
    const float* g_in  = (const float*)d_in[2];
    const float* b_in  = (const float*)d_in[3];
    const float* cb    = (const float*)d_in[4];
    const float* v_out = (const float*)d_in[5];
    const float* g_out = (const float*)d_in[6];
    const float* b_out = (const float*)d_in[7];
    float* out = (float*)d_out;

    bool full = out_size >= (LOSS_OFF + 2);
    float* codes_out = full ? (out + ZQ_ELEMS) : nullptr;

    const int SMEM_PA = 66048;   // (8192 + 8192 + 128) floats
    cudaFuncSetAttribute(proj_argmax_kernel,
                         cudaFuncAttributeMaxDynamicSharedMemorySize, SMEM_PA);

    prep_weights_kernel<<<NSCALES*1600, 128>>>(v_in, g_in, v_out, g_out, cb);

    const int scales[NSCALES] = {4, 2, 1, 1};
    for (int i = 0; i < NSCALES; i++) {
        int s = scales[i];
        int use_zf = (s > 1) ? 1 : 0;
        if (use_zf) {
            int fl = 2049 / s;
            fft_filter_kernel<<<NROWS/2, 512>>>(z, (i == 0) ? 1 : 0, fl);
        }
        proj_argmax_kernel<<<dim3(T/128, B), 256, SMEM_PA>>>(i, use_zf, b_in, codes_out);
        int mode = (i == 0) ? 0 : ((i == NSCALES-1) ? 2 : 1);
        loss_outproj_kernel<<<dim3(T/128, B), 256>>>(i, mode, cb + (size_t)i*CS*CD,
                                                     b_out + i*D, z, out);
    }
    if (full) reduce_loss_kernel<<<1, 1024>>>(out + LOSS_OFF);
}